// round 8
// baseline (speedup 1.0000x reference)
#include <cuda_runtime.h>
#include <cuda_bf16.h>

// Output: 8192 x 8192 fp32, zeros except diag(triggers * mask).
//
// Pure-write fill at the HBM write-drain ceiling (~7 TB/s). All read-elision
// and eviction-hint variants measured neutral-or-worse in the timed loop
// (all ~256MB drains to DRAM regardless of direction). This version removes
// the last identifiable waste: wave-tail imbalance. Grid-stride persistent
// layout: 1184 blocks (148 SMs x 8 resident), each warp loops over
// 2048-float chunks -> tail granularity ~one chunk instead of ~one wave.

static constexpr int N = 8192;                  // row = 8192 floats = 32 KB
static constexpr int FLOATS_PER_CHUNK = 2048;   // quarter-row per warp-iteration
static constexpr int ITERS = 8;                 // 8 x (32 lanes x 32B) = 2048 floats
static constexpr size_t NUM_CHUNKS = (size_t)N * N / FLOATS_PER_CHUNK;  // 32768
static constexpr int BLOCKS = 148 * 8;          // 1184: fully resident grid
static constexpr int TPB = 256;                 // 8 warps/block, 64 warps/SM
static constexpr unsigned TOTAL_WARPS = BLOCKS * (TPB / 32);  // 9472

__device__ __forceinline__ void stg256_zero(float* p) {
    asm volatile("st.global.v8.f32 [%0], {%1,%1,%1,%1,%1,%1,%1,%1};"
                 :: "l"(p), "f"(0.0f) : "memory");
}

__global__ void __launch_bounds__(TPB)
fill_diag_kernel(const float* __restrict__ triggers,
                 const int* __restrict__ mask,
                 float* __restrict__ out) {
    const unsigned tid  = blockIdx.x * TPB + threadIdx.x;
    const unsigned wgid = tid >> 5;          // global warp id
    const unsigned lane = tid & 31;

    for (size_t chunk = wgid; chunk < NUM_CHUNKS; chunk += TOTAL_WARPS) {
        // This warp-iteration's region: floats [startf, startf + 2048),
        // which lies within a single row (2048 | 8192).
        const size_t startf = chunk * FLOATS_PER_CHUNK;

        // ---- Diagonal ownership + early input load (hides under stores) ----
        const unsigned r  = (unsigned)(startf >> 13);   // row (N = 2^13)
        const unsigned c0 = (unsigned)(startf & (N - 1));
        const unsigned d  = r - c0;                     // wraps large if r < c0
        const bool owner  = (d < (unsigned)FLOATS_PER_CHUNK) &&
                            (((d >> 3) & 31) == lane);
        float dval = 0.0f;
        if (owner) dval = triggers[r] * (float)mask[r];

        // ---- Bulk zero: each STG.256 is a contiguous 1KB warp wavefront ----
        float* base = out + startf + (size_t)lane * 8;
#pragma unroll
        for (int i = 0; i < ITERS; i++)
            stg256_zero(base + (size_t)i * 256);

        // ---- Diagonal fix-up (same thread zeroed this address above) ----
        if (owner) out[startf + d] = dval;
    }
}

extern "C" void kernel_launch(void* const* d_in, const int* in_sizes, int n_in,
                              void* d_out, int out_size) {
    const float* triggers = (const float*)d_in[0];
    const int*   mask     = (const int*)d_in[1];
    float*       out      = (float*)d_out;

    fill_diag_kernel<<<BLOCKS, TPB>>>(triggers, mask, out);
}

// round 9
// speedup vs baseline: 1.0998x; 1.0998x over previous
#include <cuda_runtime.h>
#include <cuda_bf16.h>

// Output: 8192 x 8192 fp32, zeros except diag(triggers * mask).
//
// Final form: pure-write fill at the HBM write-drain ceiling (~7 TB/s).
// Measured across 8 variants (memset node, float4, v8, evict hints,
// read-elision, hot/stream hybrid, persistent grid): the one-shot v8 grid
// is fastest; all byte-reduction schemes fail structurally (dirty L2 lines
// drain eagerly; reads cost the same as writes; state caching is banned).
// One-shot 4096x256 grid, 256-bit stores, static per-warp addressing,
// early predicated diag-input load so its DRAM latency hides under the
// store stream. Same-thread diagonal overwrite => program-order correct.

static constexpr int N = 8192;                 // row = 8192 floats = 32 KB
static constexpr int FLOATS_PER_WARP = 2048;   // quarter-row per warp
static constexpr int ITERS = 8;                // 8 x (32 lanes x 32B) = 2048 floats

__device__ __forceinline__ void stg256_zero(float* p) {
    asm volatile("st.global.v8.f32 [%0], {%1,%1,%1,%1,%1,%1,%1,%1};"
                 :: "l"(p), "f"(0.0f) : "memory");
}

__global__ void __launch_bounds__(256)
fill_diag_kernel(const float* __restrict__ triggers,
                 const int* __restrict__ mask,
                 float* __restrict__ out) {
    const unsigned tid  = blockIdx.x * blockDim.x + threadIdx.x;
    const unsigned warp = tid >> 5;
    const unsigned lane = tid & 31;

    // This warp's region: floats [startf, startf + 2048) — within one row.
    const size_t startf = (size_t)warp * FLOATS_PER_WARP;

    // ---- Diagonal ownership + EARLY input load (overlaps store stream) ----
    // Row r's diagonal element (col r) is in range iff d = r - c0 in
    // [0, 2048). Owning lane for float offset d under the v8 layout is
    // ((d>>3) & 31) — the same thread that zeroes that address below.
    const unsigned r  = (unsigned)(startf >> 13);   // row (N = 2^13)
    const unsigned c0 = (unsigned)(startf & (N - 1));
    const unsigned d  = r - c0;                     // wraps large if r < c0
    const bool owner  = (d < (unsigned)FLOATS_PER_WARP) && (((d >> 3) & 31) == lane);
    float dval = 0.0f;
    if (owner) dval = triggers[r] * (float)mask[r];

    // ---- Bulk zero-fill: each STG.256 is a contiguous 1KB warp wavefront ----
    float* base = out + startf + (size_t)lane * 8;
#pragma unroll
    for (int i = 0; i < ITERS; i++)
        stg256_zero(base + (size_t)i * 256);

    // ---- Diagonal fix-up (register-only dependency; same-thread ordering) ----
    if (owner) out[startf + d] = dval;
}

extern "C" void kernel_launch(void* const* d_in, const int* in_sizes, int n_in,
                              void* d_out, int out_size) {
    const float* triggers = (const float*)d_in[0];
    const int*   mask     = (const int*)d_in[1];
    float*       out      = (float*)d_out;

    // 67,108,864 floats; 2048 per warp => 32768 warps => 4096 blocks of 256.
    const int blocks = (int)(((size_t)N * N / FLOATS_PER_WARP * 32) / 256);
    fill_diag_kernel<<<blocks, 256>>>(triggers, mask, out);
}

// round 10
// speedup vs baseline: 1.1066x; 1.0062x over previous
#include <cuda_runtime.h>
#include <cuda_bf16.h>

// Output: 8192 x 8192 fp32, zeros except diag(triggers * mask).
//
// FINAL: pure-write fill at the HBM write-drain ceiling.
// Evidence across 9 measured variants (memset node, float4, v8, evict
// hints, read-elision, hot/stream hybrid, persistent grid, early-load):
//  - every full-write variant lands at 41.1-41.9us total; effective write
//    rate ~6.8-7.0 TB/s on three independent mechanisms => physical ceiling
//  - every DRAM-byte-reduction scheme is neutral or worse (dirty L2 lines
//    drain eagerly; reads cost the same as writes; no policy window;
//    determinism rules ban cross-call state)
// Best-measured config (R3, 41.09us): one-shot 4096x256 grid, STG.256
// zero stores (1KB contiguous per warp instruction), diagonal overwritten
// afterwards by the same thread that zeroed it (program-order correct).

static constexpr int N = 8192;                 // row = 8192 floats = 32 KB
static constexpr int FLOATS_PER_WARP = 2048;   // quarter-row per warp
static constexpr int ITERS = 8;                // 8 x (32 lanes x 32B) = 2048 floats

__device__ __forceinline__ void stg256_zero(float* p) {
    asm volatile("st.global.v8.f32 [%0], {%1,%1,%1,%1,%1,%1,%1,%1};"
                 :: "l"(p), "f"(0.0f) : "memory");
}

__global__ void __launch_bounds__(256)
fill_diag_kernel(const float* __restrict__ triggers,
                 const int* __restrict__ mask,
                 float* __restrict__ out) {
    const unsigned tid  = blockIdx.x * blockDim.x + threadIdx.x;
    const unsigned warp = tid >> 5;
    const unsigned lane = tid & 31;

    // This warp's region: floats [startf, startf + 2048) — within one row.
    const size_t startf = (size_t)warp * FLOATS_PER_WARP;
    float* base = out + startf + (size_t)lane * 8;

    // ---- Bulk zero-fill: each STG.256 is a contiguous 1KB warp wavefront ----
#pragma unroll
    for (int i = 0; i < ITERS; i++)
        stg256_zero(base + (size_t)i * 256);

    // ---- Diagonal fix-up ----
    // Warp region lies within one row (2048 | 8192). Row r's diagonal
    // element (col r) is in range iff d = r - c0 in [0, 2048). Owning lane
    // for float offset d under the v8 layout is ((d>>3) & 31) — the same
    // thread that zeroed that address above, so program order guarantees
    // the final value. Only 32 of 32768 warps take this branch.
    const unsigned r  = (unsigned)(startf >> 13);   // row (N = 2^13)
    const unsigned c0 = (unsigned)(startf & (N - 1));
    const unsigned d  = r - c0;                     // wraps large if r < c0
    if (d < (unsigned)FLOATS_PER_WARP && ((d >> 3) & 31) == lane) {
        out[startf + d] = triggers[r] * (float)mask[r];
    }
}

extern "C" void kernel_launch(void* const* d_in, const int* in_sizes, int n_in,
                              void* d_out, int out_size) {
    const float* triggers = (const float*)d_in[0];
    const int*   mask     = (const int*)d_in[1];
    float*       out      = (float*)d_out;

    // 67,108,864 floats; 2048 per warp => 32768 warps => 4096 blocks of 256.
    const int blocks = (int)(((size_t)N * N / FLOATS_PER_WARP * 32) / 256);
    fill_diag_kernel<<<blocks, 256>>>(triggers, mask, out);
}

// round 11
// speedup vs baseline: 1.1126x; 1.0054x over previous
#include <cuda_runtime.h>
#include <cuda_bf16.h>

// Output: 8192 x 8192 fp32, zeros except diag(triggers * mask).
//
// Terminal experiment: same best-measured one-shot 4096x256 / STG.256
// layout, but with WRITE-THROUGH stores (st.global.wt). All prior variants
// write-allocate into L2 and then eagerly drain dirty lines to DRAM; wt
// skips the dirty-line bookkeeping and pushes stores straight toward the
// memory point. DRAM byte count is identical (268MB); if LTS allocate/
// drain serialization was a co-limiter this wins, otherwise it's neutral
// and the R3 kernel (41.09us) stands as final.

static constexpr int N = 8192;                 // row = 8192 floats = 32 KB
static constexpr int FLOATS_PER_WARP = 2048;   // quarter-row per warp
static constexpr int ITERS = 8;                // 8 x (32 lanes x 32B) = 2048 floats

__device__ __forceinline__ void stg256_zero_wt(float* p) {
    asm volatile("st.global.wt.v8.f32 [%0], {%1,%1,%1,%1,%1,%1,%1,%1};"
                 :: "l"(p), "f"(0.0f) : "memory");
}

__global__ void __launch_bounds__(256)
fill_diag_kernel(const float* __restrict__ triggers,
                 const int* __restrict__ mask,
                 float* __restrict__ out) {
    const unsigned tid  = blockIdx.x * blockDim.x + threadIdx.x;
    const unsigned warp = tid >> 5;
    const unsigned lane = tid & 31;

    // This warp's region: floats [startf, startf + 2048) — within one row.
    const size_t startf = (size_t)warp * FLOATS_PER_WARP;
    float* base = out + startf + (size_t)lane * 8;

    // ---- Bulk zero-fill: 1KB contiguous per STG.256 warp wavefront ----
#pragma unroll
    for (int i = 0; i < ITERS; i++)
        stg256_zero_wt(base + (size_t)i * 256);

    // ---- Diagonal fix-up ----
    // Warp region lies within one row (2048 | 8192). Row r's diagonal
    // element (col r) is in range iff d = r - c0 in [0, 2048). Owning lane
    // under the v8 layout is ((d>>3) & 31) — the same thread that zeroed
    // that address above, so program order gives the final value.
    const unsigned r  = (unsigned)(startf >> 13);   // row (N = 2^13)
    const unsigned c0 = (unsigned)(startf & (N - 1));
    const unsigned d  = r - c0;                     // wraps large if r < c0
    if (d < (unsigned)FLOATS_PER_WARP && ((d >> 3) & 31) == lane) {
        out[startf + d] = triggers[r] * (float)mask[r];
    }
}

extern "C" void kernel_launch(void* const* d_in, const int* in_sizes, int n_in,
                              void* d_out, int out_size) {
    const float* triggers = (const float*)d_in[0];
    const int*   mask     = (const int*)d_in[1];
    float*       out      = (float*)d_out;

    // 67,108,864 floats; 2048 per warp => 32768 warps => 4096 blocks of 256.
    const int blocks = (int)(((size_t)N * N / FLOATS_PER_WARP * 32) / 256);
    fill_diag_kernel<<<blocks, 256>>>(triggers, mask, out);
}